// round 4
// baseline (speedup 1.0000x reference)
#include <cuda_runtime.h>
#include <cuda_bf16.h>
#include <cstddef>
#include <math.h>

// ---------------------------------------------------------------------------
// VQ-VAE forward, fp32 + packed f32x2 FMA (sm_103a FFMA2), GB300.
// Per-accumulator chain order identical to R2/R3 (ci ascending, tap order),
// so VQ argmin decisions are bit-stable.
// ---------------------------------------------------------------------------

#define NB 32

typedef unsigned long long ull;

__device__ __forceinline__ ull pk2(float v) {
    ull r; asm("mov.b64 %0, {%1, %1};" : "=l"(r) : "f"(v)); return r;
}
__device__ __forceinline__ void fma2(ull& d, ull a, ull b) {
    asm("fma.rn.f32x2 %0, %1, %2, %0;" : "+l"(d) : "l"(a), "l"(b));
}
__device__ __forceinline__ float2 up2(ull v) {
    float2 r; asm("mov.b64 {%0, %1}, %2;" : "=f"(r.x), "=f"(r.y) : "l"(v)); return r;
}

__device__ float g_A[32u*64u*128u*128u];   // h1 / deconv1 out
__device__ float g_B[32u*128u*64u*64u];    // h2 / decoder trunk
__device__ float g_C[32u*128u*64u*64u];    // encoder trunk
__device__ float g_T[32u*32u*64u*64u];     // res hidden
__device__ float g_Z[32u*64u*64u*64u];     // z
__device__ float g_Q[32u*64u*64u*64u];     // straight-through quantized
__device__ float g_CN[512];
__device__ double g_LOSS;

// ---------------------------------------------------------------------------
// conv 3x3 s1 p1 at 64x64. 128 threads, thread: 2(y)x4(x) px, 8 cout.
// Tile 32x32. ci chunks of 8.
// ---------------------------------------------------------------------------
template<int CIN, int COUT, bool RELU_IN>
__global__ void __launch_bounds__(128) conv3v3_k(const float* __restrict__ in,
                                                 const float* __restrict__ w,
                                                 const float* __restrict__ b,
                                                 float* __restrict__ out)
{
    constexpr int COG = COUT / 8;
    constexpr int CHUNK = 8;
    __shared__ float  s_in[CHUNK][34][36];
    __shared__ float2 s_w[CHUNK][9][4];

    const int tid = threadIdx.x;
    const int tx = tid & 7, ty = tid >> 3;          // tx 0..7 (x gran 4), ty 0..15 (y gran 2)
    const int x0 = blockIdx.x * 32, y0 = blockIdx.y * 32;
    const int n  = blockIdx.z / COG;
    const int cg = blockIdx.z % COG;

    ull acc[2][4][4];
    #pragma unroll
    for (int py = 0; py < 2; py++)
        #pragma unroll
        for (int qx = 0; qx < 4; qx++)
            #pragma unroll
            for (int p = 0; p < 4; p++)
                acc[py][qx][p] = 0ull;

    const float* ip = in + (size_t)n * CIN * 4096;

    #pragma unroll 1
    for (int cc = 0; cc < CIN; cc += CHUNK) {
        __syncthreads();
        for (int i = tid; i < CHUNK * 9 * 4; i += 128) {
            int ci = i / 36, r = i % 36, k = r / 4, p = r % 4;
            const float* wp = w + ((size_t)(cg * 8 + 2 * p) * CIN + cc + ci) * 9 + k;
            s_w[ci][k][p] = make_float2(wp[0], wp[CIN * 9]);
        }
        for (int i = tid; i < CHUNK * 34 * 34; i += 128) {
            int ci = i / 1156, r = i % 1156, yy = r / 34, xx = r % 34;
            int gy = y0 - 1 + yy, gx = x0 - 1 + xx;
            float v = 0.f;
            if ((unsigned)gy < 64u && (unsigned)gx < 64u)
                v = ip[(size_t)(cc + ci) * 4096 + gy * 64 + gx];
            if (RELU_IN) v = fmaxf(v, 0.f);
            s_in[ci][yy][xx] = v;
        }
        __syncthreads();

        #pragma unroll 1
        for (int ci = 0; ci < CHUNK; ci++) {
            // 4 rows x 6 cols of inputs, packed
            ull iv[4][6];
            #pragma unroll
            for (int r = 0; r < 4; r++)
                #pragma unroll
                for (int c = 0; c < 6; c++)
                    iv[r][c] = pk2(s_in[ci][2 * ty + r][4 * tx + c]);

            #pragma unroll
            for (int k = 0; k < 9; k++) {
                const int ky = k / 3, kx = k % 3;
                const ull* wq = reinterpret_cast<const ull*>(&s_w[ci][k][0]);
                ull wv0 = wq[0], wv1 = wq[1], wv2 = wq[2], wv3 = wq[3];
                #pragma unroll
                for (int py = 0; py < 2; py++)
                    #pragma unroll
                    for (int qx = 0; qx < 4; qx++) {
                        ull inp = iv[py + ky][qx + kx];
                        fma2(acc[py][qx][0], inp, wv0);
                        fma2(acc[py][qx][1], inp, wv1);
                        fma2(acc[py][qx][2], inp, wv2);
                        fma2(acc[py][qx][3], inp, wv3);
                    }
            }
        }
    }

    #pragma unroll
    for (int p = 0; p < 4; p++) {
        const int co = cg * 8 + 2 * p;
        const float b0 = b[co], b1 = b[co + 1];
        float* o0 = out + ((size_t)n * COUT + co) * 4096;
        float* o1 = o0 + 4096;
        #pragma unroll
        for (int py = 0; py < 2; py++)
            #pragma unroll
            for (int qx = 0; qx < 4; qx++) {
                float2 v = up2(acc[py][qx][p]);
                int off = (y0 + 2 * ty + py) * 64 + x0 + 4 * tx + qx;
                o0[off] = __fadd_rn(v.x, b0);
                o1[off] = __fadd_rn(v.y, b1);
            }
    }
}

// ---------------------------------------------------------------------------
// conv 4x4 s2 p1 (64ch 128x128 -> 128ch 64x64). 128 threads, 2x4 px, 8 cout.
// ci chunks of 2.
// ---------------------------------------------------------------------------
template<int CIN, int COUT, int HOUT, bool RELU_OUT>
__global__ void __launch_bounds__(128) conv4v3_k(const float* __restrict__ in,
                                                 const float* __restrict__ w,
                                                 const float* __restrict__ b,
                                                 float* __restrict__ out)
{
    constexpr int HIN = HOUT * 2;
    constexpr int COG = COUT / 8;
    constexpr int CHUNK = 2;
    __shared__ float  s_in[CHUNK][66][68];
    __shared__ float2 s_w[CHUNK][16][4];

    const int tid = threadIdx.x;
    const int tx = tid & 7, ty = tid >> 3;
    const int x0 = blockIdx.x * 32, y0 = blockIdx.y * 32;
    const int n  = blockIdx.z / COG;
    const int cg = blockIdx.z % COG;

    ull acc[2][4][4];
    #pragma unroll
    for (int py = 0; py < 2; py++)
        #pragma unroll
        for (int qx = 0; qx < 4; qx++)
            #pragma unroll
            for (int p = 0; p < 4; p++)
                acc[py][qx][p] = 0ull;

    const float* ip = in + (size_t)n * CIN * HIN * HIN;

    #pragma unroll 1
    for (int cc = 0; cc < CIN; cc += CHUNK) {
        __syncthreads();
        for (int i = tid; i < CHUNK * 16 * 4; i += 128) {
            int ci = i / 64, r = i % 64, k = r / 4, p = r % 4;
            const float* wp = w + ((size_t)(cg * 8 + 2 * p) * CIN + cc + ci) * 16 + k;
            s_w[ci][k][p] = make_float2(wp[0], wp[CIN * 16]);
        }
        for (int i = tid; i < CHUNK * 66 * 66; i += 128) {
            int ci = i / 4356, r = i % 4356, yy = r / 66, xx = r % 66;
            int gy = 2 * y0 - 1 + yy, gx = 2 * x0 - 1 + xx;
            float v = 0.f;
            if ((unsigned)gy < (unsigned)HIN && (unsigned)gx < (unsigned)HIN)
                v = ip[(size_t)(cc + ci) * HIN * HIN + gy * HIN + gx];
            s_in[ci][yy][xx] = v;
        }
        __syncthreads();

        #pragma unroll 1
        for (int ci = 0; ci < CHUNK; ci++) {
            #pragma unroll
            for (int k = 0; k < 16; k++) {
                const int ky = k / 4, kx = k % 4;
                const ull* wq = reinterpret_cast<const ull*>(&s_w[ci][k][0]);
                ull wv0 = wq[0], wv1 = wq[1], wv2 = wq[2], wv3 = wq[3];
                #pragma unroll
                for (int py = 0; py < 2; py++)
                    #pragma unroll
                    for (int qx = 0; qx < 4; qx++) {
                        // out px (2ty+py, 4tx+qx) -> in (4ty+2py+ky, 8tx+2qx+kx)
                        ull inp = pk2(s_in[ci][4 * ty + 2 * py + ky][8 * tx + 2 * qx + kx]);
                        fma2(acc[py][qx][0], inp, wv0);
                        fma2(acc[py][qx][1], inp, wv1);
                        fma2(acc[py][qx][2], inp, wv2);
                        fma2(acc[py][qx][3], inp, wv3);
                    }
            }
        }
    }

    #pragma unroll
    for (int p = 0; p < 4; p++) {
        const int co = cg * 8 + 2 * p;
        const float b0 = b[co], b1 = b[co + 1];
        float* o0 = out + ((size_t)n * COUT + co) * HOUT * HOUT;
        float* o1 = o0 + HOUT * HOUT;
        #pragma unroll
        for (int py = 0; py < 2; py++)
            #pragma unroll
            for (int qx = 0; qx < 4; qx++) {
                float2 v = up2(acc[py][qx][p]);
                float r0 = __fadd_rn(v.x, b0), r1 = __fadd_rn(v.y, b1);
                if (RELU_OUT) { r0 = fmaxf(r0, 0.f); r1 = fmaxf(r1, 0.f); }
                int off = (y0 + 2 * ty + py) * HOUT + x0 + 4 * tx + qx;
                o0[off] = r0;
                o1[off] = r1;
            }
    }
}

// ---------------------------------------------------------------------------
// First conv 4x4 s2 p1 (3ch 256 -> 64ch 128), scalar (CIN=3).
// ---------------------------------------------------------------------------
template<int CIN, int COUT, int HOUT, bool RELU_OUT>
__global__ void __launch_bounds__(256) conv4s2_k(const float* __restrict__ in,
                                                 const float* __restrict__ w,
                                                 const float* __restrict__ b,
                                                 float* __restrict__ out)
{
    constexpr int HIN = HOUT * 2;
    constexpr int COG = COUT / 4;
    __shared__ float s_in[66][67];
    __shared__ float s_w[4][CIN][16];

    const int tid = threadIdx.x;
    const int tx = tid & 15, ty = tid >> 4;
    const int x0 = blockIdx.x * 32, y0 = blockIdx.y * 32;
    const int n  = blockIdx.z / COG;
    const int cg = blockIdx.z % COG;

    for (int i = tid; i < 4 * CIN * 16; i += 256) {
        int co = i / (CIN * 16), r = i % (CIN * 16);
        s_w[co][r / 16][r % 16] = w[(size_t)(cg * 4 + co) * CIN * 16 + r];
    }

    float acc[2][2][4];
    #pragma unroll
    for (int py = 0; py < 2; py++)
        #pragma unroll
        for (int px = 0; px < 2; px++)
            #pragma unroll
            for (int co = 0; co < 4; co++)
                acc[py][px][co] = 0.f;

    const float* ip = in + (size_t)n * CIN * HIN * HIN;
    for (int ci = 0; ci < CIN; ci++) {
        __syncthreads();
        const float* p = ip + (size_t)ci * HIN * HIN;
        for (int i = tid; i < 66 * 66; i += 256) {
            int yy = i / 66, xx = i % 66;
            int gy = 2 * y0 - 1 + yy, gx = 2 * x0 - 1 + xx;
            float v = 0.f;
            if ((unsigned)gy < (unsigned)HIN && (unsigned)gx < (unsigned)HIN)
                v = p[gy * HIN + gx];
            s_in[yy][xx] = v;
        }
        __syncthreads();
        #pragma unroll
        for (int py = 0; py < 2; py++)
            #pragma unroll
            for (int px = 0; px < 2; px++) {
                const int ly = ty + 16 * py, lx = tx + 16 * px;
                #pragma unroll
                for (int ky = 0; ky < 4; ky++)
                    #pragma unroll
                    for (int kx = 0; kx < 4; kx++) {
                        float v = s_in[2 * ly + ky][2 * lx + kx];
                        #pragma unroll
                        for (int co = 0; co < 4; co++)
                            acc[py][px][co] = fmaf(v, s_w[co][ci][ky * 4 + kx], acc[py][px][co]);
                    }
            }
    }

    #pragma unroll
    for (int co = 0; co < 4; co++) {
        float bias = b[cg * 4 + co];
        float* op = out + ((size_t)n * COUT + cg * 4 + co) * HOUT * HOUT;
        #pragma unroll
        for (int py = 0; py < 2; py++)
            #pragma unroll
            for (int px = 0; px < 2; px++) {
                float v = __fadd_rn(acc[py][px][co], bias);
                if (RELU_OUT) v = fmaxf(v, 0.f);
                op[(y0 + ty + 16 * py) * HOUT + x0 + tx + 16 * px] = v;
            }
    }
}

// ---------------------------------------------------------------------------
// conv 1x1 at 64x64, f32x2. Thread: 8 px (2x float4) x 8 cout.
// ---------------------------------------------------------------------------
template<int CIN, int COUT, bool RELU_IN, bool RESID>
__global__ void __launch_bounds__(256) conv1x1v3_k(const float* __restrict__ in,
                                                   const float* __restrict__ w,
                                                   const float* __restrict__ b,
                                                   float* __restrict__ out,
                                                   const float* __restrict__ resid)
{
    constexpr int COG = COUT / 8;
    __shared__ float2 s_w[CIN][4];
    const int tid = threadIdx.x;
    const int n  = blockIdx.z / COG;
    const int cg = blockIdx.z % COG;

    for (int i = tid; i < CIN * 4; i += 256) {
        int ci = i / 4, p = i % 4;
        s_w[ci][p] = make_float2(w[(size_t)(cg * 8 + 2 * p) * CIN + ci],
                                 w[(size_t)(cg * 8 + 2 * p + 1) * CIN + ci]);
    }
    __syncthreads();

    const int px0 = blockIdx.x * 2048 + tid * 8;
    const float* ip = in + (size_t)n * CIN * 4096 + px0;

    ull acc[8][4];
    #pragma unroll
    for (int j = 0; j < 8; j++)
        #pragma unroll
        for (int p = 0; p < 4; p++)
            acc[j][p] = 0ull;

    #pragma unroll 2
    for (int ci = 0; ci < CIN; ci++) {
        float4 va = *(const float4*)(ip + (size_t)ci * 4096);
        float4 vb = *(const float4*)(ip + (size_t)ci * 4096 + 4);
        if (RELU_IN) {
            va.x = fmaxf(va.x, 0.f); va.y = fmaxf(va.y, 0.f);
            va.z = fmaxf(va.z, 0.f); va.w = fmaxf(va.w, 0.f);
            vb.x = fmaxf(vb.x, 0.f); vb.y = fmaxf(vb.y, 0.f);
            vb.z = fmaxf(vb.z, 0.f); vb.w = fmaxf(vb.w, 0.f);
        }
        ull iv[8];
        iv[0] = pk2(va.x); iv[1] = pk2(va.y); iv[2] = pk2(va.z); iv[3] = pk2(va.w);
        iv[4] = pk2(vb.x); iv[5] = pk2(vb.y); iv[6] = pk2(vb.z); iv[7] = pk2(vb.w);
        const ull* wq = reinterpret_cast<const ull*>(&s_w[ci][0]);
        ull w0 = wq[0], w1 = wq[1], w2 = wq[2], w3 = wq[3];
        #pragma unroll
        for (int j = 0; j < 8; j++) {
            fma2(acc[j][0], iv[j], w0);
            fma2(acc[j][1], iv[j], w1);
            fma2(acc[j][2], iv[j], w2);
            fma2(acc[j][3], iv[j], w3);
        }
    }

    #pragma unroll
    for (int p = 0; p < 4; p++) {
        const int co = cg * 8 + 2 * p;
        const float b0 = b[co], b1 = b[co + 1];
        float* o0 = out + ((size_t)n * COUT + co) * 4096 + px0;
        float* o1 = o0 + 4096;
        float r0[8], r1[8];
        #pragma unroll
        for (int j = 0; j < 8; j++) {
            float2 v = up2(acc[j][p]);
            r0[j] = __fadd_rn(v.x, b0);
            r1[j] = __fadd_rn(v.y, b1);
        }
        if (RESID) {
            const float* q0 = resid + ((size_t)n * COUT + co) * 4096 + px0;
            #pragma unroll
            for (int h = 0; h < 2; h++) {
                float4 s0 = *(const float4*)(q0 + 4 * h);
                float4 s1 = *(const float4*)(q0 + 4096 + 4 * h);
                r0[4*h+0] = __fadd_rn(s0.x, r0[4*h+0]); r0[4*h+1] = __fadd_rn(s0.y, r0[4*h+1]);
                r0[4*h+2] = __fadd_rn(s0.z, r0[4*h+2]); r0[4*h+3] = __fadd_rn(s0.w, r0[4*h+3]);
                r1[4*h+0] = __fadd_rn(s1.x, r1[4*h+0]); r1[4*h+1] = __fadd_rn(s1.y, r1[4*h+1]);
                r1[4*h+2] = __fadd_rn(s1.z, r1[4*h+2]); r1[4*h+3] = __fadd_rn(s1.w, r1[4*h+3]);
            }
        }
        #pragma unroll
        for (int h = 0; h < 2; h++) {
            *(float4*)(o0 + 4 * h) = make_float4(r0[4*h], r0[4*h+1], r0[4*h+2], r0[4*h+3]);
            *(float4*)(o1 + 4 * h) = make_float4(r1[4*h], r1[4*h+1], r1[4*h+2], r1[4*h+3]);
        }
    }
}

// ---------------------------------------------------------------------------
// deconv1 k=4 s=2 p=1 (64x64 -> 128x128, 128->64ch), f32x2 cout pairs.
// Tile 32(y)x64(x); thread: 2x4 px (spacing 16), 8 cout. RELU in+out.
// ---------------------------------------------------------------------------
template<int CIN>
__global__ void __launch_bounds__(256) deconv1v2_k(const float* __restrict__ in,
                                                   const float* __restrict__ w,
                                                   const float* __restrict__ b,
                                                   float* __restrict__ out)
{
    constexpr int COUT = 64, HIN = 64, HOUT = 128;
    constexpr int COG = COUT / 8;
    constexpr int CHUNK = 8;
    __shared__ float  s_in[CHUNK][18][36];
    __shared__ float2 s_w[CHUNK][16][4];

    const int tid = threadIdx.x;
    const int tx = tid & 15, ty = tid >> 4;
    const int x0 = blockIdx.x * 64, y0 = blockIdx.y * 32;
    const int n  = blockIdx.z / COG;
    const int cg = blockIdx.z % COG;

    ull acc[2][4][4];
    #pragma unroll
    for (int py = 0; py < 2; py++)
        #pragma unroll
        for (int qx = 0; qx < 4; qx++)
            #pragma unroll
            for (int p = 0; p < 4; p++)
                acc[py][qx][p] = 0ull;

    const int iyb = y0 / 2 - 1, ixb = x0 / 2 - 1;
    const float* ip = in + (size_t)n * CIN * HIN * HIN;

    const int ky0 = (ty + 1) & 1, kx0 = (tx + 1) & 1;

    #pragma unroll 1
    for (int cc = 0; cc < CIN; cc += CHUNK) {
        __syncthreads();
        for (int i = tid; i < CHUNK * 16 * 4; i += 256) {
            int ci = i / 64, r = i % 64, k = r / 4, p = r % 4;
            const float* wp = w + ((size_t)(cc + ci) * COUT + cg * 8 + 2 * p) * 16 + k;
            s_w[ci][k][p] = make_float2(wp[0], wp[16]);
        }
        for (int i = tid; i < CHUNK * 18 * 34; i += 256) {
            int ci = i / 612, r = i % 612, yy = r / 34, xx = r % 34;
            int gy = iyb + yy, gx = ixb + xx;
            float v = 0.f;
            if ((unsigned)gy < (unsigned)HIN && (unsigned)gx < (unsigned)HIN)
                v = ip[(size_t)(cc + ci) * HIN * HIN + gy * HIN + gx];
            v = fmaxf(v, 0.f);
            s_in[ci][yy][xx] = v;
        }
        __syncthreads();

        #pragma unroll 1
        for (int ci = 0; ci < CHUNK; ci++) {
            #pragma unroll
            for (int a = 0; a < 2; a++) {
                const int ky = ky0 + 2 * a;
                #pragma unroll
                for (int c2 = 0; c2 < 2; c2++) {
                    const int kx = kx0 + 2 * c2;
                    const ull* wq = reinterpret_cast<const ull*>(&s_w[ci][ky * 4 + kx][0]);
                    ull wv0 = wq[0], wv1 = wq[1], wv2 = wq[2], wv3 = wq[3];
                    #pragma unroll
                    for (int py = 0; py < 2; py++) {
                        const int ly = ty + 16 * py;
                        const int iyl = ((ly + 1 - ky) >> 1) + 1;
                        #pragma unroll
                        for (int qx = 0; qx < 4; qx++) {
                            const int lx = tx + 16 * qx;
                            const int ixl = ((lx + 1 - kx) >> 1) + 1;
                            ull inp = pk2(s_in[ci][iyl][ixl]);
                            fma2(acc[py][qx][0], inp, wv0);
                            fma2(acc[py][qx][1], inp, wv1);
                            fma2(acc[py][qx][2], inp, wv2);
                            fma2(acc[py][qx][3], inp, wv3);
                        }
                    }
                }
            }
        }
    }

    #pragma unroll
    for (int p = 0; p < 4; p++) {
        const int co = cg * 8 + 2 * p;
        const float b0 = b[co], b1 = b[co + 1];
        float* o0 = out + ((size_t)n * COUT + co) * HOUT * HOUT;
        float* o1 = o0 + HOUT * HOUT;
        #pragma unroll
        for (int py = 0; py < 2; py++)
            #pragma unroll
            for (int qx = 0; qx < 4; qx++) {
                float2 v = up2(acc[py][qx][p]);
                float r0 = fmaxf(__fadd_rn(v.x, b0), 0.f);
                float r1 = fmaxf(__fadd_rn(v.y, b1), 0.f);
                int off = (y0 + ty + 16 * py) * HOUT + x0 + tx + 16 * qx;
                o0[off] = r0;
                o1[off] = r1;
            }
    }
}

// ---------------------------------------------------------------------------
// deconv2 k=4 s=2 p=1 (128x128 -> 256x256, 64->3ch) + tanh.
// f32x2 cout pair (0,1) + scalar co2. Tile 32x32 out, 2x2 px, 256 threads.
// ---------------------------------------------------------------------------
__global__ void __launch_bounds__(256) deconv2v2_k(const float* __restrict__ in,
                                                   const float* __restrict__ w,
                                                   const float* __restrict__ b,
                                                   float* __restrict__ out)
{
    constexpr int CIN = 64, COUT = 3, HIN = 128, HOUT = 256;
    constexpr int CHUNK = 4;
    __shared__ float  s_in[CHUNK][18][20];
    __shared__ float2 s_wp[CHUNK][16];
    __shared__ float  s_w2[CHUNK][16];

    const int tid = threadIdx.x;
    const int tx = tid & 15, ty = tid >> 4;
    const int x0 = blockIdx.x * 32, y0 = blockIdx.y * 32;
    const int n  = blockIdx.z;

    ull   accp[2][2];
    float acc2[2][2];
    #pragma unroll
    for (int py = 0; py < 2; py++)
        #pragma unroll
        for (int px = 0; px < 2; px++) { accp[py][px] = 0ull; acc2[py][px] = 0.f; }

    const int iyb = y0 / 2 - 1, ixb = x0 / 2 - 1;
    const float* ip = in + (size_t)n * CIN * HIN * HIN;
    const int ky0 = (ty + 1) & 1, kx0 = (tx + 1) & 1;

    #pragma unroll 1
    for (int cc = 0; cc < CIN; cc += CHUNK) {
        __syncthreads();
        for (int i = tid; i < CHUNK * 16 * 2; i += 256) {
            int half = i / (CHUNK * 16), r = i % (CHUNK * 16);
            int ci = r / 16, k = r % 16;
            const float* wp = w + ((size_t)(cc + ci) * COUT) * 16 + k;
            if (half == 0) s_wp[ci][k] = make_float2(wp[0], wp[16]);
            else           s_w2[ci][k] = wp[32];
        }
        for (int i = tid; i < CHUNK * 18 * 18; i += 256) {
            int ci = i / 324, r = i % 324, yy = r / 18, xx = r % 18;
            int gy = iyb + yy, gx = ixb + xx;
            float v = 0.f;
            if ((unsigned)gy < (unsigned)HIN && (unsigned)gx < (unsigned)HIN)
                v = ip[(size_t)(cc + ci) * HIN * HIN + gy * HIN + gx];
            s_in[ci][yy][xx] = v;
        }
        __syncthreads();

        #pragma unroll 1
        for (int ci = 0; ci < CHUNK; ci++) {
            #pragma unroll
            for (int a = 0; a < 2; a++) {
                const int ky = ky0 + 2 * a;
                #pragma unroll
                for (int c2 = 0; c2 < 2; c2++) {
                    const int kx = kx0 + 2 * c2;
                    ull wvp = *reinterpret_cast<const ull*>(&s_wp[ci][ky * 4 + kx]);
                    float wv2 = s_w2[ci][ky * 4 + kx];
                    #pragma unroll
                    for (int py = 0; py < 2; py++) {
                        const int ly = ty + 16 * py;
                        const int iyl = ((ly + 1 - ky) >> 1) + 1;
                        #pragma unroll
                        for (int px = 0; px < 2; px++) {
                            const int lx = tx + 16 * px;
                            const int ixl = ((lx + 1 - kx) >> 1) + 1;
                            float v = s_in[ci][iyl][ixl];
                            fma2(accp[py][px], pk2(v), wvp);
                            acc2[py][px] = fmaf(v, wv2, acc2[py][px]);
                        }
                    }
                }
            }
        }
    }

    const float b0 = b[0], b1 = b[1], b2 = b[2];
    float* o0 = out + (size_t)n * 3 * 65536;
    float* o1 = o0 + 65536;
    float* o2 = o1 + 65536;
    #pragma unroll
    for (int py = 0; py < 2; py++)
        #pragma unroll
        for (int px = 0; px < 2; px++) {
            float2 v = up2(accp[py][px]);
            int off = (y0 + ty + 16 * py) * HOUT + x0 + tx + 16 * px;
            o0[off] = tanhf(__fadd_rn(v.x, b0));
            o1[off] = tanhf(__fadd_rn(v.y, b1));
            o2[off] = tanhf(__fadd_rn(acc2[py][px], b2));
        }
}

// ---------------------------------------------------------------------------
// VQ (codebook norms, argmin + loss, finalize)
// ---------------------------------------------------------------------------
__global__ void cnorm_k(const float* __restrict__ cb, float* __restrict__ cn)
{
    int c = blockIdx.x * 256 + threadIdx.x;
    if (c < 512) {
        float s = 0.f;
        for (int d = 0; d < 64; d++) {
            float v = cb[c * 64 + d];
            s = __fadd_rn(s, __fmul_rn(v, v));
        }
        cn[c] = s;
    }
}

__global__ void zero_loss_k(double* loss) { *loss = 0.0; }

__global__ void __launch_bounds__(256) vq_k(const float* __restrict__ z,
                                            const float* __restrict__ cb,
                                            const float* __restrict__ cn,
                                            float* __restrict__ q,
                                            double* __restrict__ loss)
{
    __shared__ float s_cT[64][128];   // [d][c] for one 128-code chunk
    __shared__ float s_n[128];
    __shared__ double s_red[256];

    const int tid = threadIdx.x;
    const int vec = blockIdx.x * 256 + tid;
    const int n = vec >> 12, px = vec & 4095;
    const float* zp = z + (size_t)n * 64 * 4096 + px;

    float zr[64];
    #pragma unroll
    for (int d = 0; d < 64; d++) zr[d] = zp[(size_t)d * 4096];

    float sumz2 = 0.f;
    #pragma unroll
    for (int d = 0; d < 64; d++)
        sumz2 = __fadd_rn(sumz2, __fmul_rn(zr[d], zr[d]));

    float best = 3.4e38f;
    int bi = 0;

    for (int ch = 0; ch < 4; ch++) {
        __syncthreads();
        for (int i = tid; i < 128 * 64; i += 256) {
            int c = i >> 6, d = i & 63;
            s_cT[d][c] = cb[(size_t)(ch * 128 + c) * 64 + d];
        }
        if (tid < 128) s_n[tid] = cn[ch * 128 + tid];
        __syncthreads();

        for (int c0 = 0; c0 < 128; c0 += 16) {
            ull a[8];
            #pragma unroll
            for (int j = 0; j < 8; j++) a[j] = 0ull;
            #pragma unroll
            for (int d = 0; d < 64; d++) {
                ull zv = pk2(zr[d]);
                const ulonglong2* cq = reinterpret_cast<const ulonglong2*>(&s_cT[d][c0]);
                ulonglong2 q0 = cq[0], q1 = cq[1], q2 = cq[2], q3 = cq[3];
                fma2(a[0], zv, q0.x); fma2(a[1], zv, q0.y);
                fma2(a[2], zv, q1.x); fma2(a[3], zv, q1.y);
                fma2(a[4], zv, q2.x); fma2(a[5], zv, q2.y);
                fma2(a[6], zv, q3.x); fma2(a[7], zv, q3.y);
            }
            #pragma unroll
            for (int j = 0; j < 8; j++) {
                float2 dots = up2(a[j]);
                int c = ch * 128 + c0 + 2 * j;
                float t0 = __fadd_rn(sumz2, -2.f * dots.x);
                float d0 = __fadd_rn(t0, s_n[c0 + 2 * j]);
                if (d0 < best) { best = d0; bi = c; }
                float t1 = __fadd_rn(sumz2, -2.f * dots.y);
                float d1 = __fadd_rn(t1, s_n[c0 + 2 * j + 1]);
                if (d1 < best) { best = d1; bi = c + 1; }
            }
        }
    }

    const float* cp = cb + (size_t)bi * 64;
    float* qp = q + (size_t)n * 64 * 4096 + px;
    double sum = 0.0;
    #pragma unroll
    for (int d = 0; d < 64; d++) {
        float qv = __ldg(cp + d);
        float df = __fadd_rn(qv, -zr[d]);
        sum += (double)df * (double)df;
        qp[(size_t)d * 4096] = __fadd_rn(zr[d], df);   // straight-through
    }

    s_red[tid] = sum;
    __syncthreads();
    for (int s = 128; s > 0; s >>= 1) {
        if (tid < s) s_red[tid] += s_red[tid + s];
        __syncthreads();
    }
    if (tid == 0) atomicAdd(loss, s_red[0]);
}

__global__ void finalize_k(const double* __restrict__ loss, float* __restrict__ out, int idx)
{
    out[idx] = (float)((*loss) * 1.25 / 8388608.0);
}

// ---------------------------------------------------------------------------
// Host orchestration
// ---------------------------------------------------------------------------
extern "C" void kernel_launch(void* const* d_in, const int* in_sizes, int n_in,
                              void* d_out, int out_size)
{
    const float* x    = (const float*)d_in[0];
    const float* ew1  = (const float*)d_in[1];
    const float* eb1  = (const float*)d_in[2];
    const float* ew2  = (const float*)d_in[3];
    const float* eb2  = (const float*)d_in[4];
    const float* ew3  = (const float*)d_in[5];
    const float* eb3  = (const float*)d_in[6];
    const float* erw1 = (const float*)d_in[7];
    const float* erb1 = (const float*)d_in[8];
    const float* erw2 = (const float*)d_in[9];
    const float* erb2 = (const float*)d_in[10];
    const float* pvqw = (const float*)d_in[11];
    const float* pvqb = (const float*)d_in[12];
    const float* cb   = (const float*)d_in[13];
    const float* dw1  = (const float*)d_in[14];
    const float* db1  = (const float*)d_in[15];
    const float* drw1 = (const float*)d_in[16];
    const float* drb1 = (const float*)d_in[17];
    const float* drw2 = (const float*)d_in[18];
    const float* drb2 = (const float*)d_in[19];
    const float* t1w  = (const float*)d_in[20];
    const float* t1b  = (const float*)d_in[21];
    const float* t2w  = (const float*)d_in[22];
    const float* t2b  = (const float*)d_in[23];
    float* out = (float*)d_out;

    float *A, *B, *C, *T, *Z, *Q, *CN;
    double* L;
    cudaGetSymbolAddress((void**)&A, g_A);
    cudaGetSymbolAddress((void**)&B, g_B);
    cudaGetSymbolAddress((void**)&C, g_C);
    cudaGetSymbolAddress((void**)&T, g_T);
    cudaGetSymbolAddress((void**)&Z, g_Z);
    cudaGetSymbolAddress((void**)&Q, g_Q);
    cudaGetSymbolAddress((void**)&CN, g_CN);
    cudaGetSymbolAddress((void**)&L, g_LOSS);

    // Encoder
    conv4s2_k<3, 64, 128, true><<<dim3(4, 4, NB * 16), 256>>>(x, ew1, eb1, A);
    conv4v3_k<64, 128, 64, true><<<dim3(2, 2, NB * 16), 128>>>(A, ew2, eb2, B);
    conv3v3_k<128, 128, false><<<dim3(2, 2, NB * 16), 128>>>(B, ew3, eb3, C);
    for (int i = 0; i < 2; i++) {
        conv3v3_k<128, 32, true><<<dim3(2, 2, NB * 4), 128>>>(
            C, erw1 + (size_t)i * 32 * 128 * 9, erb1 + i * 32, T);
        conv1x1v3_k<32, 128, true, true><<<dim3(2, 1, NB * 16), 256>>>(
            T, erw2 + (size_t)i * 128 * 32, erb2 + i * 128, C, C);
    }
    conv1x1v3_k<128, 64, true, false><<<dim3(2, 1, NB * 8), 256>>>(C, pvqw, pvqb, Z, nullptr);

    // VQ
    zero_loss_k<<<1, 1>>>(L);
    cnorm_k<<<2, 256>>>(cb, CN);
    vq_k<<<512, 256>>>(Z, cb, CN, Q, L);

    // Decoder
    conv3v3_k<64, 128, false><<<dim3(2, 2, NB * 16), 128>>>(Q, dw1, db1, B);
    for (int i = 0; i < 2; i++) {
        conv3v3_k<128, 32, true><<<dim3(2, 2, NB * 4), 128>>>(
            B, drw1 + (size_t)i * 32 * 128 * 9, drb1 + i * 32, T);
        conv1x1v3_k<32, 128, true, true><<<dim3(2, 1, NB * 16), 256>>>(
            T, drw2 + (size_t)i * 128 * 32, drb2 + i * 128, B, B);
    }
    deconv1v2_k<128><<<dim3(2, 4, NB * 8), 256>>>(B, t1w, t1b, A);
    deconv2v2_k<<<dim3(8, 8, NB), 256>>>(A, t2w, t2b, out);

    if (out_size > 32 * 3 * 256 * 256)
        finalize_k<<<1, 1>>>(L, out, out_size - 1);
}